// round 10
// baseline (speedup 1.0000x reference)
#include <cuda_runtime.h>
#include <cuda_fp16.h>
#include <math.h>
#include <stdint.h>

// Problem constants
#define B     16384
#define NROWS 32768          // B * C, C = 2
#define D     1024
#define NGRP  128            // N_SUBJECTS * N_LABELS
#define NL    8
#define NSUB  16
#define NBLK  64             // B / 256

// ---------------- scratch (device globals; no allocation allowed) ----------
__device__ int   g_gid[B];
__device__ int   g_cntB[NGRP];
__device__ int   g_off[NGRP + 1];
__device__ int   g_cur[NGRP];
__device__ int   g_perm[B];
__device__ float g_cent[NGRP * D];                // fp32 centroid accumulator
__device__ __align__(16) __half g_cent_h[NGRP * D];   // fp16 centroid (B operand)
__device__ float g_cnorm[NGRP];
__device__ float g_sim[(size_t)NROWS * NGRP];     // 16 MB
__device__ float g_rownorm[NROWS];
__device__ float g_msqrt[NGRP];
__device__ float g_rdens[NGRP];                   // reciprocal density
__device__ float g_loss;

// ---------------- helpers (base PTX only — compute_103-safe) ---------------
__device__ __forceinline__ uint32_t smem_u32(const void* p) {
    uint32_t a;
    asm("{ .reg .u64 t; cvta.to.shared.u64 t, %1; cvt.u32.u64 %0, t; }"
        : "=r"(a) : "l"(p));
    return a;
}
__device__ __forceinline__ uint32_t sw128(uint32_t off) {
    return off ^ ((off >> 3) & 0x70);
}
#define CP_ASYNC16(dst, src) \
    asm volatile("cp.async.cg.shared.global [%0], [%1], 16;" \
                 :: "r"(dst), "l"(src) : "memory")
#define CP_COMMIT() asm volatile("cp.async.commit_group;" ::: "memory")
#define CP_WAIT0()  asm volatile("cp.async.wait_group 0;" ::: "memory")

#define LDSM4(r, a)                                                          \
    asm volatile("ldmatrix.sync.aligned.m8n8.x4.shared.b16 {%0,%1,%2,%3}, [%4];" \
        : "=r"((r)[0]), "=r"((r)[1]), "=r"((r)[2]), "=r"((r)[3]) : "r"(a))
#define LDSM2(r, a)                                                          \
    asm volatile("ldmatrix.sync.aligned.m8n8.x2.shared.b16 {%0,%1}, [%2];"   \
        : "=r"((r)[0]), "=r"((r)[1]) : "r"(a))
#define MMA_F16(c, a, bq)                                                    \
    asm volatile("mma.sync.aligned.m16n8k16.row.col.f32.f16.f16.f32 "       \
        "{%0,%1,%2,%3},{%4,%5,%6,%7},{%8,%9},{%0,%1,%2,%3};"                 \
        : "+f"((c)[0]), "+f"((c)[1]), "+f"((c)[2]), "+f"((c)[3])             \
        : "r"((a)[0]), "r"((a)[1]), "r"((a)[2]), "r"((a)[3]),                \
          "r"((bq)[0]), "r"((bq)[1]))

// ---------------- 0: zero accumulators (graph-replay safe) -----------------
__global__ void k_init() {
    int idx = blockIdx.x * 256 + threadIdx.x;
    if (idx < NGRP * D) g_cent[idx] = 0.f;
    if (idx < NGRP) { g_msqrt[idx] = 0.f; g_cntB[idx] = 0; }
    if (idx == 0) g_loss = 0.f;
}

// ---------------- 1: gid + warp-aggregated global histogram ------------------
__global__ void k_hist2(const int* __restrict__ subj, const int* __restrict__ lab) {
    int t = threadIdx.x, lane = t & 31;
    int b = blockIdx.x * 256 + t;
    int g = subj[b] * NL + lab[b];
    g_gid[b] = g;
    unsigned mask = __match_any_sync(0xffffffffu, g);
    int leader = __ffs(mask) - 1;
    if (lane == leader) atomicAdd(&g_cntB[g], __popc(mask));
}

// ---------------- 2: scan (1 block) ------------------------------------------
__global__ void k_scan2() {
    __shared__ int off[NGRP + 1];
    int g = threadIdx.x;
    if (g == 0) {
        int a = 0;
        for (int i = 0; i < NGRP; i++) { off[i] = a; a += g_cntB[i]; }
        off[NGRP] = a;
    }
    __syncthreads();
    g_off[g] = off[g];
    g_cur[g] = off[g];
    if (g == 0) g_off[NGRP] = off[NGRP];
}

// ---------------- 3: scatter (warp-aggregated cursor; order-free) ------------
__global__ void k_scatter() {
    int t = threadIdx.x, lane = t & 31;
    int b = blockIdx.x * 256 + t;
    int g = g_gid[b];
    unsigned mask = __match_any_sync(0xffffffffu, g);
    int leader = __ffs(mask) - 1;
    int rank = __popc(mask & ((1u << lane) - 1u));
    int base = 0;
    if (lane == leader) base = atomicAdd(&g_cur[g], __popc(mask));
    base = __shfl_sync(0xffffffffu, base, leader);
    g_perm[base + rank] = b;
}

// ---------------- 4a: centroid gather (8-way row slices, fp32 atomic) --------
__global__ void k_centroid(const float* __restrict__ X) {
    int g = blockIdx.y;
    int d = blockIdx.x * 256 + threadIdx.x;
    int slice = blockIdx.z;
    int s = g_off[g], e = g_off[g + 1];
    float acc = 0.f;
    int i = s + slice;
    for (; i + 16 <= e; i += 16) {
        const float* p0 = X + (size_t)g_perm[i]     * (2 * D);
        const float* p1 = X + (size_t)g_perm[i + 8] * (2 * D);
        acc += (p0[d] + p0[D + d]) + (p1[d] + p1[D + d]);
    }
    for (; i < e; i += 8) {
        const float* p = X + (size_t)g_perm[i] * (2 * D);
        acc += p[d] + p[D + d];
    }
    atomicAdd(&g_cent[g * D + d], acc);
}

// ---------------- 4b: centroid finalize (fp16 + ||c||^2) ---------------------
__global__ void k_centfin() {
    __shared__ float sr[256];
    int g = blockIdx.x;
    int t = threadIdx.x;
    float inv = 1.f / (2.f * (float)g_cntB[g]);
    float n = 0.f;
    #pragma unroll
    for (int j = 0; j < 4; j++) {
        int d = j * 256 + t;
        float c = g_cent[g * D + d] * inv;
        g_cent_h[g * D + d] = __float2half(c);
        n = fmaf(c, c, n);
    }
    sr[t] = n; __syncthreads();
    for (int st = 128; st > 0; st >>= 1) {
        if (t < st) sr[t] += sr[t + st];
        __syncthreads();
    }
    if (t == 0) g_cnorm[g] = sr[0];
}

// ---------------- 5: HMMA GEMM  sim = feat @ centroid^T  (+ row norms) -------
// CTA: 128(M) x 128(N), 8 warps as 4x2, warp tile 32x64.
// K chunks of 64 fp32, double-buffered SW128 smem (A fp16, B fp16).
// A converted to packed fp16 at prefetch time (uint2 abuf) -> low reg pressure,
// 2 CTAs/SM (single wave over 256 CTAs).
#define KC       64
#define TCBUF    16384                 // 128 rows x 128 bytes
#define TCSTAGE  (2 * TCBUF)           // 32 KB
#define TC_SMEM  (2 * TCSTAGE)         // 64 KB

__global__ void __launch_bounds__(256, 2) k_gemm_mma(const float* __restrict__ X) {
    extern __shared__ __align__(1024) char dsm[];
    const uint32_t smb = smem_u32(dsm);

    const int tid    = threadIdx.x;
    const int wid    = tid >> 5;
    const int lane   = tid & 31;
    const int warp_m = wid >> 1;       // 0..3
    const int warp_n = wid & 1;        // 0..1
    const int rowBase = blockIdx.x * 128;

    // loader mapping: 2 threads per row, 32 fp32 cols each
    const int r_local = tid >> 1;
    const int half    = tid & 1;
    const int rg      = rowBase + r_local;
    const float* aSrc =
        X + (size_t)((rg & (B - 1)) * 2 + (rg >> 14)) * D + half * 32;
    const __half* bhSrc = g_cent_h + r_local * D + half * 32;
    const uint32_t aStOff[8] = {
        sw128(r_local * 128 + half * 64 + 0),  sw128(r_local * 128 + half * 64 + 8),
        sw128(r_local * 128 + half * 64 + 16), sw128(r_local * 128 + half * 64 + 24),
        sw128(r_local * 128 + half * 64 + 32), sw128(r_local * 128 + half * 64 + 40),
        sw128(r_local * 128 + half * 64 + 48), sw128(r_local * 128 + half * 64 + 56)};
    const uint32_t bStOff[4] = {
        sw128(r_local * 128 + half * 64 + 0),  sw128(r_local * 128 + half * 64 + 16),
        sw128(r_local * 128 + half * 64 + 32), sw128(r_local * 128 + half * 64 + 48)};

    float c[2][8][4];
    #pragma unroll
    for (int mi = 0; mi < 2; mi++)
        #pragma unroll
        for (int ni = 0; ni < 8; ni++)
            #pragma unroll
            for (int j = 0; j < 4; j++) c[mi][ni][j] = 0.f;
    float nrm = 0.f;

    // ldmatrix lane addressing (within-tile offsets)
    const int a_tile = lane >> 3, a_rr = lane & 7;
    const int l15 = lane & 15;

    // ---- prologue: chunk 0 (load A, convert to packed fp16) ----
    uint2 abuf[8];
    #pragma unroll
    for (int i = 0; i < 8; i++) {
        float4 v = *(const float4*)(aSrc + i * 4);
        nrm = fmaf(v.x, v.x, nrm); nrm = fmaf(v.y, v.y, nrm);
        nrm = fmaf(v.z, v.z, nrm); nrm = fmaf(v.w, v.w, nrm);
        __half2 h01(__float2half(v.x), __float2half(v.y));
        __half2 h23(__float2half(v.z), __float2half(v.w));
        abuf[i] = make_uint2(*(uint32_t*)&h01, *(uint32_t*)&h23);
    }
    {
        uint32_t bh0 = smb + TCBUF;
        #pragma unroll
        for (int i = 0; i < 4; i++)
            CP_ASYNC16(bh0 + bStOff[i], (const char*)(bhSrc + i * 8));
        CP_COMMIT();
    }

    for (int kt = 0; kt < D / KC; kt++) {
        const uint32_t st = smb + (kt & 1) * TCSTAGE;
        const uint32_t Ah = st, Bh = st + TCBUF;

        // STS packed A(kt)
        #pragma unroll
        for (int i = 0; i < 8; i++)
            asm volatile("st.shared.v2.b32 [%0], {%1,%2};" ::
                         "r"(Ah + aStOff[i]), "r"(abuf[i].x), "r"(abuf[i].y)
                         : "memory");
        CP_WAIT0();          // B(kt) landed
        __syncthreads();     // stage (kt&1) fully populated

        // prefetch chunk kt+1 (load + convert + pack A; cp.async B)
        if (kt + 1 < D / KC) {
            #pragma unroll
            for (int i = 0; i < 8; i++) {
                float4 v = *(const float4*)(aSrc + (kt + 1) * KC + i * 4);
                nrm = fmaf(v.x, v.x, nrm); nrm = fmaf(v.y, v.y, nrm);
                nrm = fmaf(v.z, v.z, nrm); nrm = fmaf(v.w, v.w, nrm);
                __half2 h01(__float2half(v.x), __float2half(v.y));
                __half2 h23(__float2half(v.z), __float2half(v.w));
                abuf[i] = make_uint2(*(uint32_t*)&h01, *(uint32_t*)&h23);
            }
            const uint32_t nst = smb + ((kt + 1) & 1) * TCSTAGE;
            #pragma unroll
            for (int i = 0; i < 4; i++)
                CP_ASYNC16(nst + TCBUF + bStOff[i],
                           (const char*)(bhSrc + (kt + 1) * KC + i * 8));
            CP_COMMIT();
        }

        // compute: 4 k16 steps
        #pragma unroll
        for (int ks = 0; ks < 4; ks++) {
            const int kb = ks * 16;
            uint32_t ah[2][4];
            #pragma unroll
            for (int mi = 0; mi < 2; mi++) {
                int mrow = warp_m * 32 + mi * 16 + ((a_tile & 1) << 3) + a_rr;
                int kcol = kb + ((a_tile >> 1) << 3);
                uint32_t off = sw128((uint32_t)(mrow * 128 + kcol * 2));
                LDSM4(ah[mi], Ah + off);
            }
            #pragma unroll
            for (int ni = 0; ni < 8; ni++) {
                int nrow = warp_n * 64 + ni * 8 + (l15 & 7);
                int kcol = kb + ((l15 >> 3) << 3);
                uint32_t boff = sw128((uint32_t)(nrow * 128 + kcol * 2));
                uint32_t bh[2];
                LDSM2(bh, Bh + boff);
                MMA_F16(c[0][ni], ah[0], bh);
                MMA_F16(c[1][ni], ah[1], bh);
            }
        }
        __syncthreads();     // protect stage reuse (STS of kt+2)
    }

    // row norms (pairs of threads share a row)
    nrm += __shfl_xor_sync(0xffffffffu, nrm, 1);
    if (half == 0) g_rownorm[rg] = nrm;

    // epilogue: write C fragments
    const int mq = lane >> 2, nq = (lane & 3) * 2;
    #pragma unroll
    for (int mi = 0; mi < 2; mi++) {
        #pragma unroll
        for (int ni = 0; ni < 8; ni++) {
            int m = rowBase + warp_m * 32 + mi * 16 + mq;
            int n = warp_n * 64 + ni * 8 + nq;
            float2 v0 = make_float2(c[mi][ni][0], c[mi][ni][1]);
            float2 v1 = make_float2(c[mi][ni][2], c[mi][ni][3]);
            *(float2*)(g_sim + (size_t)m * NGRP + n)       = v0;
            *(float2*)(g_sim + (size_t)(m + 8) * NGRP + n) = v1;
        }
    }
}

// ---------------- 6: per-row distance -> sqrt -> group mean accum -----------
__global__ void k_dist() {
    int r = blockIdx.x * blockDim.x + threadIdx.x;
    if (r < NROWS) {
        int b = r & (B - 1);
        int g = g_gid[b];
        float s    = g_sim[(size_t)r * NGRP + g];
        float d2   = g_rownorm[r] - 2.f * s + g_cnorm[g];
        float dist = sqrtf(fmaxf(d2, 0.f));
        atomicAdd(&g_msqrt[g], sqrtf(dist));
    }
}

// ---------------- 7: density (1 block, 128 threads) -------------------------
__global__ void k_density() {
    __shared__ float sd[NGRP];
    __shared__ float sr[NGRP];
    int t = threadIdx.x;
    float cnt  = 2.f * (float)g_cntB[t];
    float dens = (g_msqrt[t] / cnt) / logf(cnt + 10.f);

    sr[t] = dens; __syncthreads();
    for (int s = 64; s > 0; s >>= 1) {
        if (t < s) sr[t] = fmaxf(sr[t], sr[t + s]);
        __syncthreads();
    }
    float dmax = sr[0]; __syncthreads();
    if (cnt <= 1.f) dens = dmax;

    sd[t] = dens; __syncthreads();
    for (int ksz = 2; ksz <= NGRP; ksz <<= 1) {
        for (int j = ksz >> 1; j > 0; j >>= 1) {
            int ixj = t ^ j;
            if (ixj > t) {
                float x = sd[t], y = sd[ixj];
                bool up = ((t & ksz) == 0);
                if ((x > y) == up) { sd[t] = y; sd[ixj] = x; }
            }
            __syncthreads();
        }
    }
    float lo = sd[12]  + 0.7f * (sd[13]  - sd[12]);
    float hi = sd[114] + 0.3f * (sd[115] - sd[114]);
    float dc = fminf(fmaxf(dens, lo), hi);

    sr[t] = dc; __syncthreads();
    for (int s = 64; s > 0; s >>= 1) {
        if (t < s) sr[t] += sr[t + s];
        __syncthreads();
    }
    float mean = sr[0] * (1.f / (float)NGRP);
    g_rdens[t] = mean / (0.1f * dc);
}

// ---------------- 8: loss (one warp per row) ---------------------------------
__global__ void __launch_bounds__(256) k_loss(const int* __restrict__ subj,
                                              const int* __restrict__ lab) {
    __shared__ float sdens[NGRP];
    __shared__ float swsum[8];
    int t = threadIdx.x, lane = t & 31, w = t >> 5;
    if (t < NGRP) sdens[t] = g_rdens[t];
    __syncthreads();

    int r = blockIdx.x * 8 + w;
    int b = r & (B - 1);
    int sub = subj[b], la = lab[b];
    const float* row = g_sim + (size_t)r * NGRP;

    float v[4];
    float mx = -1e30f;
    #pragma unroll
    for (int q = 0; q < 4; q++) {
        int g = q * 32 + lane;
        v[q] = row[g] * sdens[g];
        mx = fmaxf(mx, v[q]);
    }
    #pragma unroll
    for (int o = 16; o; o >>= 1) mx = fmaxf(mx, __shfl_xor_sync(0xffffffffu, mx, o));

    float p[4];
    float possum = 0.f, m2 = -1e30f;
    #pragma unroll
    for (int q = 0; q < 4; q++) {
        int g = q * 32 + lane;
        bool msk = ((g >> 3) != sub) && ((g & 7) == la);
        float val = v[q] - mx;
        p[q] = msk ? val : 0.f;
        possum += msk ? val : 0.f;
        m2 = fmaxf(m2, p[q]);
    }
    #pragma unroll
    for (int o = 16; o; o >>= 1) m2 = fmaxf(m2, __shfl_xor_sync(0xffffffffu, m2, o));

    float se = 0.f;
    #pragma unroll
    for (int q = 0; q < 4; q++) se += expf(p[q] - m2);
    #pragma unroll
    for (int o = 16; o; o >>= 1) {
        se     += __shfl_xor_sync(0xffffffffu, se, o);
        possum += __shfl_xor_sync(0xffffffffu, possum, o);
    }
    float lse  = m2 + logf(se);
    float loss = lse - possum * (1.f / 15.f);   // mask.sum = NSUB-1 = 15 always

    if (lane == 0) swsum[w] = loss;
    __syncthreads();
    if (t == 0) {
        float s = 0.f;
        #pragma unroll
        for (int i = 0; i < 8; i++) s += swsum[i];
        atomicAdd(&g_loss, s);
    }
}

// ---------------- 9: finalize -------------------------------------------------
__global__ void k_final(float* __restrict__ out) {
    out[0] = g_loss * (1.f / (float)NROWS);
}

// ---------------- launcher ----------------------------------------------------
extern "C" void kernel_launch(void* const* d_in, const int* in_sizes, int n_in,
                              void* d_out, int out_size) {
    const float* X    = (const float*)d_in[0];
    const int*   subj = (const int*)  d_in[1];
    const int*   lab  = (const int*)  d_in[2];
    float*       out  = (float*)d_out;

    cudaFuncSetAttribute(k_gemm_mma, cudaFuncAttributeMaxDynamicSharedMemorySize,
                         TC_SMEM);

    k_init    <<<(NGRP * D + 255) / 256, 256>>>();
    k_hist2   <<<NBLK, 256>>>(subj, lab);
    k_scan2   <<<1, NGRP>>>();
    k_scatter <<<NBLK, 256>>>();
    k_centroid<<<dim3(4, NGRP, 8), 256>>>(X);
    k_centfin <<<NGRP, 256>>>();
    k_gemm_mma<<<NROWS / 128, 256, TC_SMEM>>>(X);
    k_dist    <<<NROWS / 256, 256>>>();
    k_density <<<1, NGRP>>>();
    k_loss    <<<NROWS / 8, 256>>>(subj, lab);
    k_final   <<<1, 1>>>(out);
}

// round 11
// speedup vs baseline: 1.0311x; 1.0311x over previous
#include <cuda_runtime.h>
#include <cuda_fp16.h>
#include <math.h>
#include <stdint.h>

// Problem constants
#define B     16384
#define NROWS 32768          // B * C, C = 2
#define D     1024
#define NGRP  128            // N_SUBJECTS * N_LABELS
#define NL    8
#define NSUB  16
#define NBLK  64             // sort blocks (B / 256)

// ---------------- scratch (device globals; no allocation allowed) ----------
__device__ int   g_gid[B];
__device__ int   g_bhist[NBLK * NGRP];
__device__ int   g_bbase[NBLK * NGRP];
__device__ int   g_cntB[NGRP];
__device__ int   g_off[NGRP + 1];
__device__ int   g_perm[B];
__device__ float g_cent8[8 * NGRP * D];           // per-slice centroid partials (4 MB)
__device__ __align__(16) __half g_cent_h[NGRP * D];   // fp16 centroid (B operand)
__device__ float g_cnorm[NGRP];
__device__ float g_sim[(size_t)NROWS * NGRP];     // 16 MB
__device__ float g_rownorm[NROWS];
__device__ float g_msqrt[NGRP];
__device__ float g_rdens[NGRP];                   // reciprocal density
__device__ float g_loss;
__device__ int   g_ticket;

// ---------------- helpers (base PTX only — compute_103-safe) ---------------
__device__ __forceinline__ uint32_t smem_u32(const void* p) {
    uint32_t a;
    asm("{ .reg .u64 t; cvta.to.shared.u64 t, %1; cvt.u32.u64 %0, t; }"
        : "=r"(a) : "l"(p));
    return a;
}
__device__ __forceinline__ uint32_t sw128(uint32_t off) {
    return off ^ ((off >> 3) & 0x70);
}
#define CP_ASYNC16(dst, src) \
    asm volatile("cp.async.cg.shared.global [%0], [%1], 16;" \
                 :: "r"(dst), "l"(src) : "memory")
#define CP_COMMIT() asm volatile("cp.async.commit_group;" ::: "memory")
#define CP_WAIT0()  asm volatile("cp.async.wait_group 0;" ::: "memory")

#define LDSM4(r, a)                                                          \
    asm volatile("ldmatrix.sync.aligned.m8n8.x4.shared.b16 {%0,%1,%2,%3}, [%4];" \
        : "=r"((r)[0]), "=r"((r)[1]), "=r"((r)[2]), "=r"((r)[3]) : "r"(a))
#define LDSM2(r, a)                                                          \
    asm volatile("ldmatrix.sync.aligned.m8n8.x2.shared.b16 {%0,%1}, [%2];"   \
        : "=r"((r)[0]), "=r"((r)[1]) : "r"(a))
#define MMA_F16(c, a, bq)                                                    \
    asm volatile("mma.sync.aligned.m16n8k16.row.col.f32.f16.f16.f32 "       \
        "{%0,%1,%2,%3},{%4,%5,%6,%7},{%8,%9},{%0,%1,%2,%3};"                 \
        : "+f"((c)[0]), "+f"((c)[1]), "+f"((c)[2]), "+f"((c)[3])             \
        : "r"((a)[0]), "r"((a)[1]), "r"((a)[2]), "r"((a)[3]),                \
          "r"((bq)[0]), "r"((bq)[1]))

// ---------------- 0: zero accumulators (graph-replay safe) -----------------
__global__ void k_init() {
    int t = threadIdx.x;
    if (t < NGRP) g_msqrt[t] = 0.f;
    if (t == 0) { g_loss = 0.f; g_ticket = 0; }
}

// ---------------- 1: gid + per-block histogram -------------------------------
__global__ void k_hist2(const int* __restrict__ subj, const int* __restrict__ lab) {
    __shared__ int h[NGRP];
    int t = threadIdx.x;
    if (t < NGRP) h[t] = 0;
    __syncthreads();
    int b = blockIdx.x * 256 + t;
    int g = subj[b] * NL + lab[b];
    g_gid[b] = g;
    atomicAdd(&h[g], 1);
    __syncthreads();
    if (t < NGRP) g_bhist[blockIdx.x * NGRP + t] = h[t];
}

// ---------------- 2: scan (1 block, 128 threads) -----------------------------
__global__ void k_scan2() {
    __shared__ int cnt[NGRP];
    __shared__ int off[NGRP + 1];
    int g = threadIdx.x;
    int s = 0;
    for (int bk = 0; bk < NBLK; bk++) s += g_bhist[bk * NGRP + g];
    cnt[g] = s;
    g_cntB[g] = s;
    __syncthreads();
    if (g == 0) {
        int a = 0;
        for (int i = 0; i < NGRP; i++) { off[i] = a; a += cnt[i]; }
        off[NGRP] = a;
    }
    __syncthreads();
    int run = off[g];
    g_off[g] = run;
    if (g == 0) g_off[NGRP] = off[NGRP];
    for (int bk = 0; bk < NBLK; bk++) {
        g_bbase[bk * NGRP + g] = run;
        run += g_bhist[bk * NGRP + g];
    }
}

// ---------------- 3: stable scatter -------------------------------------------
__global__ void k_scatter() {
    __shared__ int swc[8 * NGRP];
    int t = threadIdx.x, wid = t >> 5, lane = t & 31;
    for (int i = t; i < 8 * NGRP; i += 256) swc[i] = 0;
    __syncthreads();
    int b = blockIdx.x * 256 + t;
    int g = g_gid[b];
    unsigned mask = __match_any_sync(0xffffffffu, g);
    unsigned lt = (1u << lane) - 1u;
    int rank = __popc(mask & lt);
    if (rank == 0) swc[wid * NGRP + g] = __popc(mask);
    __syncthreads();
    int pre = 0;
    for (int w = 0; w < wid; w++) pre += swc[w * NGRP + g];
    g_perm[g_bbase[blockIdx.x * NGRP + g] + pre + rank] = b;
}

// ---------------- 4a: centroid gather (8-way row slices, private partials) ---
__global__ void k_centroid(const float* __restrict__ X) {
    int g = blockIdx.y;
    int d = blockIdx.x * 256 + threadIdx.x;
    int slice = blockIdx.z;
    int s = g_off[g], e = g_off[g + 1];
    float acc = 0.f;
    int i = s + slice;
    for (; i + 16 <= e; i += 16) {
        const float* p0 = X + (size_t)g_perm[i]     * (2 * D);
        const float* p1 = X + (size_t)g_perm[i + 8] * (2 * D);
        acc += (p0[d] + p0[D + d]) + (p1[d] + p1[D + d]);
    }
    for (; i < e; i += 8) {
        const float* p = X + (size_t)g_perm[i] * (2 * D);
        acc += p[d] + p[D + d];
    }
    g_cent8[(slice * NGRP + g) * D + d] = acc;
}

// ---------------- 4b: centroid finalize (sum slices + fp16 + ||c||^2) --------
__global__ void k_centfin() {
    __shared__ float sr[256];
    int g = blockIdx.x;
    int t = threadIdx.x;
    float inv = 1.f / (2.f * (float)g_cntB[g]);
    float n = 0.f;
    #pragma unroll
    for (int j = 0; j < 4; j++) {
        int d = j * 256 + t;
        float c = 0.f;
        #pragma unroll
        for (int sl = 0; sl < 8; sl++)
            c += g_cent8[(sl * NGRP + g) * D + d];
        c *= inv;
        g_cent_h[g * D + d] = __float2half(c);
        n = fmaf(c, c, n);
    }
    sr[t] = n; __syncthreads();
    for (int st = 128; st > 0; st >>= 1) {
        if (t < st) sr[t] += sr[t + st];
        __syncthreads();
    }
    if (t == 0) g_cnorm[g] = sr[0];
}

// ---------------- 5: HMMA GEMM  sim = feat @ centroid^T  (+ row norms) -------
// EXACT R9 kernel (141.9us) — do not modify (register-allocation sensitive).
// CTA: 128(M) x 128(N), 8 warps as 4x2, warp tile 32x64.
// K chunks of 64 fp32, double-buffered SW128 smem (A fp16, B fp16).
// 1-term fp16: C += A*B  (f32 accumulate in HMMA).
#define KC       64
#define TCBUF    16384                 // 128 rows x 128 bytes
#define TCSTAGE  (2 * TCBUF)           // 32 KB
#define TC_SMEM  (2 * TCSTAGE)         // 64 KB

__global__ void __launch_bounds__(256, 1) k_gemm_mma(const float* __restrict__ X) {
    extern __shared__ __align__(1024) char dsm[];
    const uint32_t smb = smem_u32(dsm);

    const int tid    = threadIdx.x;
    const int wid    = tid >> 5;
    const int lane   = tid & 31;
    const int warp_m = wid >> 1;       // 0..3
    const int warp_n = wid & 1;        // 0..1
    const int rowBase = blockIdx.x * 128;

    // loader mapping: 2 threads per row, 32 fp32 cols each
    const int r_local = tid >> 1;
    const int half    = tid & 1;
    const int rg      = rowBase + r_local;
    const float* aSrc =
        X + (size_t)((rg & (B - 1)) * 2 + (rg >> 14)) * D + half * 32;
    const __half* bhSrc = g_cent_h + r_local * D + half * 32;
    const uint32_t aStOff[8] = {
        sw128(r_local * 128 + half * 64 + 0),  sw128(r_local * 128 + half * 64 + 8),
        sw128(r_local * 128 + half * 64 + 16), sw128(r_local * 128 + half * 64 + 24),
        sw128(r_local * 128 + half * 64 + 32), sw128(r_local * 128 + half * 64 + 40),
        sw128(r_local * 128 + half * 64 + 48), sw128(r_local * 128 + half * 64 + 56)};
    const uint32_t bStOff[4] = {
        sw128(r_local * 128 + half * 64 + 0),  sw128(r_local * 128 + half * 64 + 16),
        sw128(r_local * 128 + half * 64 + 32), sw128(r_local * 128 + half * 64 + 48)};

    float c[2][8][4];
    #pragma unroll
    for (int mi = 0; mi < 2; mi++)
        #pragma unroll
        for (int ni = 0; ni < 8; ni++)
            #pragma unroll
            for (int j = 0; j < 4; j++) c[mi][ni][j] = 0.f;
    float nrm = 0.f;

    // ldmatrix lane addressing (within-tile offsets)
    const int a_tile = lane >> 3, a_rr = lane & 7;
    const int l15 = lane & 15;

    // ---- prologue: chunk 0 ----
    float4 abuf[8];
    #pragma unroll
    for (int i = 0; i < 8; i++) abuf[i] = *(const float4*)(aSrc + i * 4);
    {
        uint32_t bh0 = smb + TCBUF;
        #pragma unroll
        for (int i = 0; i < 4; i++)
            CP_ASYNC16(bh0 + bStOff[i], (const char*)(bhSrc + i * 8));
        CP_COMMIT();
    }

    for (int kt = 0; kt < D / KC; kt++) {
        const uint32_t st = smb + (kt & 1) * TCSTAGE;
        const uint32_t Ah = st, Bh = st + TCBUF;

        // convert + STS A(kt) (+ row-norm accumulation)
        #pragma unroll
        for (int i = 0; i < 8; i++) {
            float4 v = abuf[i];
            nrm = fmaf(v.x, v.x, nrm); nrm = fmaf(v.y, v.y, nrm);
            nrm = fmaf(v.z, v.z, nrm); nrm = fmaf(v.w, v.w, nrm);
            __half hx = __float2half(v.x);
            __half hy = __float2half(v.y);
            __half hz = __float2half(v.z);
            __half hw = __float2half(v.w);
            __half2 h01(hx, hy), h23(hz, hw);
            uint2 hv = make_uint2(*(uint32_t*)&h01, *(uint32_t*)&h23);
            asm volatile("st.shared.v2.b32 [%0], {%1,%2};" ::
                         "r"(Ah + aStOff[i]), "r"(hv.x), "r"(hv.y) : "memory");
        }
        CP_WAIT0();          // B(kt) landed
        __syncthreads();     // stage (kt&1) fully populated

        // prefetch chunk kt+1
        if (kt + 1 < D / KC) {
            #pragma unroll
            for (int i = 0; i < 8; i++)
                abuf[i] = *(const float4*)(aSrc + (kt + 1) * KC + i * 4);
            const uint32_t nst = smb + ((kt + 1) & 1) * TCSTAGE;
            #pragma unroll
            for (int i = 0; i < 4; i++)
                CP_ASYNC16(nst + TCBUF + bStOff[i],
                           (const char*)(bhSrc + (kt + 1) * KC + i * 8));
            CP_COMMIT();
        }

        // compute: 4 k16 steps
        #pragma unroll
        for (int ks = 0; ks < 4; ks++) {
            const int kb = ks * 16;
            uint32_t ah[2][4];
            #pragma unroll
            for (int mi = 0; mi < 2; mi++) {
                int mrow = warp_m * 32 + mi * 16 + ((a_tile & 1) << 3) + a_rr;
                int kcol = kb + ((a_tile >> 1) << 3);
                uint32_t off = sw128((uint32_t)(mrow * 128 + kcol * 2));
                LDSM4(ah[mi], Ah + off);
            }
            #pragma unroll
            for (int ni = 0; ni < 8; ni++) {
                int nrow = warp_n * 64 + ni * 8 + (l15 & 7);
                int kcol = kb + ((l15 >> 3) << 3);
                uint32_t boff = sw128((uint32_t)(nrow * 128 + kcol * 2));
                uint32_t bh[2];
                LDSM2(bh, Bh + boff);
                MMA_F16(c[0][ni], ah[0], bh);
                MMA_F16(c[1][ni], ah[1], bh);
            }
        }
        __syncthreads();     // protect stage reuse (STS of kt+2)
    }

    // row norms (pairs of threads share a row)
    nrm += __shfl_xor_sync(0xffffffffu, nrm, 1);
    if (half == 0) g_rownorm[rg] = nrm;

    // epilogue: write C fragments
    const int mq = lane >> 2, nq = (lane & 3) * 2;
    #pragma unroll
    for (int mi = 0; mi < 2; mi++) {
        #pragma unroll
        for (int ni = 0; ni < 8; ni++) {
            int m = rowBase + warp_m * 32 + mi * 16 + mq;
            int n = warp_n * 64 + ni * 8 + nq;
            float2 v0 = make_float2(c[mi][ni][0], c[mi][ni][1]);
            float2 v1 = make_float2(c[mi][ni][2], c[mi][ni][3]);
            *(float2*)(g_sim + (size_t)m * NGRP + n)       = v0;
            *(float2*)(g_sim + (size_t)(m + 8) * NGRP + n) = v1;
        }
    }
}

// ---------------- 6: per-row distance -> sqrt -> group mean accum -----------
__global__ void k_dist() {
    int r = blockIdx.x * blockDim.x + threadIdx.x;
    if (r < NROWS) {
        int b = r & (B - 1);
        int g = g_gid[b];
        float s    = g_sim[(size_t)r * NGRP + g];
        float d2   = g_rownorm[r] - 2.f * s + g_cnorm[g];
        float dist = sqrtf(fmaxf(d2, 0.f));
        atomicAdd(&g_msqrt[g], sqrtf(dist));
    }
}

// ---------------- 7: density (1 block, 128 threads) -------------------------
__global__ void k_density() {
    __shared__ float sd[NGRP];
    __shared__ float sr[NGRP];
    int t = threadIdx.x;
    float cnt  = 2.f * (float)g_cntB[t];
    float dens = (g_msqrt[t] / cnt) / logf(cnt + 10.f);

    sr[t] = dens; __syncthreads();
    for (int s = 64; s > 0; s >>= 1) {
        if (t < s) sr[t] = fmaxf(sr[t], sr[t + s]);
        __syncthreads();
    }
    float dmax = sr[0]; __syncthreads();
    if (cnt <= 1.f) dens = dmax;

    sd[t] = dens; __syncthreads();
    for (int ksz = 2; ksz <= NGRP; ksz <<= 1) {
        for (int j = ksz >> 1; j > 0; j >>= 1) {
            int ixj = t ^ j;
            if (ixj > t) {
                float x = sd[t], y = sd[ixj];
                bool up = ((t & ksz) == 0);
                if ((x > y) == up) { sd[t] = y; sd[ixj] = x; }
            }
            __syncthreads();
        }
    }
    float lo = sd[12]  + 0.7f * (sd[13]  - sd[12]);
    float hi = sd[114] + 0.3f * (sd[115] - sd[114]);
    float dc = fminf(fmaxf(dens, lo), hi);

    sr[t] = dc; __syncthreads();
    for (int s = 64; s > 0; s >>= 1) {
        if (t < s) sr[t] += sr[t + s];
        __syncthreads();
    }
    float mean = sr[0] * (1.f / (float)NGRP);
    g_rdens[t] = mean / (0.1f * dc);
}

// ---------------- 8: loss (one warp per row) + fused finalize ----------------
__global__ void __launch_bounds__(256) k_loss(const int* __restrict__ subj,
                                              const int* __restrict__ lab,
                                              float* __restrict__ out) {
    __shared__ float sdens[NGRP];
    __shared__ float swsum[8];
    int t = threadIdx.x, lane = t & 31, w = t >> 5;
    if (t < NGRP) sdens[t] = g_rdens[t];
    __syncthreads();

    int r = blockIdx.x * 8 + w;
    int b = r & (B - 1);
    int sub = subj[b], la = lab[b];
    const float* row = g_sim + (size_t)r * NGRP;

    float v[4];
    float mx = -1e30f;
    #pragma unroll
    for (int q = 0; q < 4; q++) {
        int g = q * 32 + lane;
        v[q] = row[g] * sdens[g];
        mx = fmaxf(mx, v[q]);
    }
    #pragma unroll
    for (int o = 16; o; o >>= 1) mx = fmaxf(mx, __shfl_xor_sync(0xffffffffu, mx, o));

    float p[4];
    float possum = 0.f, m2 = -1e30f;
    #pragma unroll
    for (int q = 0; q < 4; q++) {
        int g = q * 32 + lane;
        bool msk = ((g >> 3) != sub) && ((g & 7) == la);
        float val = v[q] - mx;
        p[q] = msk ? val : 0.f;
        possum += msk ? val : 0.f;
        m2 = fmaxf(m2, p[q]);
    }
    #pragma unroll
    for (int o = 16; o; o >>= 1) m2 = fmaxf(m2, __shfl_xor_sync(0xffffffffu, m2, o));

    float se = 0.f;
    #pragma unroll
    for (int q = 0; q < 4; q++) se += expf(p[q] - m2);
    #pragma unroll
    for (int o = 16; o; o >>= 1) {
        se     += __shfl_xor_sync(0xffffffffu, se, o);
        possum += __shfl_xor_sync(0xffffffffu, possum, o);
    }
    float lse  = m2 + logf(se);
    float loss = lse - possum * (1.f / 15.f);   // mask.sum = NSUB-1 = 15 always

    if (lane == 0) swsum[w] = loss;
    __syncthreads();
    if (t == 0) {
        float s = 0.f;
        #pragma unroll
        for (int i = 0; i < 8; i++) s += swsum[i];
        atomicAdd(&g_loss, s);
        __threadfence();
        int tk = atomicAdd(&g_ticket, 1);
        if (tk == gridDim.x - 1) {
            // all blocks' g_loss additions are visible (fence + ticket order)
            out[0] = g_loss * (1.f / (float)NROWS);
        }
    }
}

// ---------------- launcher ----------------------------------------------------
extern "C" void kernel_launch(void* const* d_in, const int* in_sizes, int n_in,
                              void* d_out, int out_size) {
    const float* X    = (const float*)d_in[0];
    const int*   subj = (const int*)  d_in[1];
    const int*   lab  = (const int*)  d_in[2];
    float*       out  = (float*)d_out;

    cudaFuncSetAttribute(k_gemm_mma, cudaFuncAttributeMaxDynamicSharedMemorySize,
                         TC_SMEM);

    k_init    <<<1, 128>>>();
    k_hist2   <<<NBLK, 256>>>(subj, lab);
    k_scan2   <<<1, NGRP>>>();
    k_scatter <<<NBLK, 256>>>();
    k_centroid<<<dim3(4, NGRP, 8), 256>>>(X);
    k_centfin <<<NGRP, 256>>>();
    k_gemm_mma<<<NROWS / 128, 256, TC_SMEM>>>(X);
    k_dist    <<<NROWS / 256, 256>>>();
    k_density <<<1, NGRP>>>();
    k_loss    <<<NROWS / 8, 256>>>(subj, lab, out);
}

// round 12
// speedup vs baseline: 1.0460x; 1.0144x over previous
#include <cuda_runtime.h>
#include <cuda_fp16.h>
#include <math.h>
#include <stdint.h>

// Problem constants
#define B     16384
#define NROWS 32768          // B * C, C = 2
#define D     1024
#define NGRP  128            // N_SUBJECTS * N_LABELS
#define NL    8
#define NSUB  16
#define NBLK  64             // sort blocks (B / 256)

// ---------------- scratch (device globals; no allocation allowed) ----------
__device__ int   g_gid[B];
__device__ int   g_bhist[NBLK * NGRP];
__device__ int   g_cntB[NGRP];
__device__ int   g_off[NGRP + 1];
__device__ int   g_perm[B];
__device__ float g_cent8[8 * NGRP * D];           // per-slice centroid partials (4 MB)
__device__ __align__(16) __half g_cent_h[NGRP * D];   // fp16 centroid (B operand)
__device__ float g_cnorm[NGRP];
__device__ float g_sim[(size_t)NROWS * NGRP];     // 16 MB
__device__ float g_rownorm[NROWS];
__device__ float g_msqrt[NGRP];
__device__ float g_rdens[NGRP];                   // reciprocal density
__device__ float g_loss;
__device__ int   g_ticket;
__device__ int   g_tick_cd[4 * NGRP];             // centroid finalize tickets

// ---------------- helpers (base PTX only — compute_103-safe) ---------------
__device__ __forceinline__ uint32_t smem_u32(const void* p) {
    uint32_t a;
    asm("{ .reg .u64 t; cvta.to.shared.u64 t, %1; cvt.u32.u64 %0, t; }"
        : "=r"(a) : "l"(p));
    return a;
}
__device__ __forceinline__ uint32_t sw128(uint32_t off) {
    return off ^ ((off >> 3) & 0x70);
}
#define CP_ASYNC16(dst, src) \
    asm volatile("cp.async.cg.shared.global [%0], [%1], 16;" \
                 :: "r"(dst), "l"(src) : "memory")
#define CP_COMMIT() asm volatile("cp.async.commit_group;" ::: "memory")
#define CP_WAIT0()  asm volatile("cp.async.wait_group 0;" ::: "memory")

#define LDSM4(r, a)                                                          \
    asm volatile("ldmatrix.sync.aligned.m8n8.x4.shared.b16 {%0,%1,%2,%3}, [%4];" \
        : "=r"((r)[0]), "=r"((r)[1]), "=r"((r)[2]), "=r"((r)[3]) : "r"(a))
#define LDSM2(r, a)                                                          \
    asm volatile("ldmatrix.sync.aligned.m8n8.x2.shared.b16 {%0,%1}, [%2];"   \
        : "=r"((r)[0]), "=r"((r)[1]) : "r"(a))
#define MMA_F16(c, a, bq)                                                    \
    asm volatile("mma.sync.aligned.m16n8k16.row.col.f32.f16.f16.f32 "       \
        "{%0,%1,%2,%3},{%4,%5,%6,%7},{%8,%9},{%0,%1,%2,%3};"                 \
        : "+f"((c)[0]), "+f"((c)[1]), "+f"((c)[2]), "+f"((c)[3])             \
        : "r"((a)[0]), "r"((a)[1]), "r"((a)[2]), "r"((a)[3]),                \
          "r"((bq)[0]), "r"((bq)[1]))

// ---------------- 1: gid + per-block histogram (+ init in block 0) -----------
__global__ void k_hist2(const int* __restrict__ subj, const int* __restrict__ lab) {
    __shared__ int h[NGRP];
    int t = threadIdx.x;
    if (t < NGRP) h[t] = 0;
    if (blockIdx.x == 0) {
        if (t < NGRP) { g_msqrt[t] = 0.f; g_cnorm[t] = 0.f; }
        g_tick_cd[t] = 0;
        g_tick_cd[t + 256] = 0;
        if (t == 0) { g_loss = 0.f; g_ticket = 0; }
    }
    __syncthreads();
    int b = blockIdx.x * 256 + t;
    int g = subj[b] * NL + lab[b];
    g_gid[b] = g;
    atomicAdd(&h[g], 1);
    __syncthreads();
    if (t < NGRP) g_bhist[blockIdx.x * NGRP + t] = h[t];
}

// ---------------- 2: scatter (per-block local scan of g_bhist) ---------------
__global__ void k_scatter() {
    __shared__ int swc[8 * NGRP];
    __shared__ int s_off[NGRP];
    __shared__ int s_base[NGRP];
    int t = threadIdx.x, wid = t >> 5, lane = t & 31;
    for (int i = t; i < 8 * NGRP; i += 256) swc[i] = 0;
    if (t < NGRP) {
        int before = 0, total = 0;
        for (int bk = 0; bk < NBLK; bk++) {
            int hh = g_bhist[bk * NGRP + t];
            before += (bk < (int)blockIdx.x) ? hh : 0;
            total += hh;
        }
        s_off[t] = total;          // totals, scanned below
        s_base[t] = before;
        if (blockIdx.x == 0) g_cntB[t] = total;
    }
    __syncthreads();
    if (t == 0) {
        int a = 0;
        for (int i = 0; i < NGRP; i++) { int c = s_off[i]; s_off[i] = a; a += c; }
    }
    __syncthreads();
    if (t < NGRP) {
        s_base[t] += s_off[t];
        if (blockIdx.x == 0) {
            g_off[t] = s_off[t];
            if (t == 0) g_off[NGRP] = B;
        }
    }
    __syncthreads();
    int b = blockIdx.x * 256 + t;
    int g = g_gid[b];
    unsigned mask = __match_any_sync(0xffffffffu, g);
    unsigned lt = (1u << lane) - 1u;
    int rank = __popc(mask & lt);
    if (rank == 0) swc[wid * NGRP + g] = __popc(mask);
    __syncthreads();
    int pre = 0;
    for (int w = 0; w < wid; w++) pre += swc[w * NGRP + g];
    g_perm[s_base[g] + pre + rank] = b;
}

// ---------------- 3: centroid gather + ticketed finalize ---------------------
// grid (4, 128, 8): dblock, group, slice. Last-arriving slice block for a
// (dblock, group) pair sums the 8 partials, writes fp16 centroid + ||c||^2.
__global__ void k_centroid(const float* __restrict__ X) {
    __shared__ float sr[256];
    __shared__ int s_last;
    int g = blockIdx.y;
    int dblk = blockIdx.x;
    int slice = blockIdx.z;
    int t = threadIdx.x;
    int d = dblk * 256 + t;
    int s = g_off[g], e = g_off[g + 1];
    float acc = 0.f;
    int i = s + slice;
    for (; i + 16 <= e; i += 16) {
        const float* p0 = X + (size_t)g_perm[i]     * (2 * D);
        const float* p1 = X + (size_t)g_perm[i + 8] * (2 * D);
        acc += (p0[d] + p0[D + d]) + (p1[d] + p1[D + d]);
    }
    for (; i < e; i += 8) {
        const float* p = X + (size_t)g_perm[i] * (2 * D);
        acc += p[d] + p[D + d];
    }
    g_cent8[(slice * NGRP + g) * D + d] = acc;
    __threadfence();
    __syncthreads();
    if (t == 0) s_last = (atomicAdd(&g_tick_cd[dblk * NGRP + g], 1) == 7) ? 1 : 0;
    __syncthreads();
    if (!s_last) return;
    __threadfence();
    float inv = 1.f / (2.f * (float)g_cntB[g]);
    float c = 0.f;
    #pragma unroll
    for (int sl = 0; sl < 8; sl++) c += g_cent8[(sl * NGRP + g) * D + d];
    c *= inv;
    g_cent_h[g * D + d] = __float2half(c);
    sr[t] = c * c; __syncthreads();
    for (int st = 128; st > 0; st >>= 1) {
        if (t < st) sr[t] += sr[t + st];
        __syncthreads();
    }
    if (t == 0) atomicAdd(&g_cnorm[g], sr[0]);
}

// ---------------- 4: HMMA GEMM  sim = feat @ centroid^T  (+ row norms) -------
// EXACT R9 kernel (141.9us) — do not modify (register-allocation sensitive).
// CTA: 128(M) x 128(N), 8 warps as 4x2, warp tile 32x64.
// K chunks of 64 fp32, double-buffered SW128 smem (A fp16, B fp16).
// 1-term fp16: C += A*B  (f32 accumulate in HMMA).
#define KC       64
#define TCBUF    16384                 // 128 rows x 128 bytes
#define TCSTAGE  (2 * TCBUF)           // 32 KB
#define TC_SMEM  (2 * TCSTAGE)         // 64 KB

__global__ void __launch_bounds__(256, 1) k_gemm_mma(const float* __restrict__ X) {
    extern __shared__ __align__(1024) char dsm[];
    const uint32_t smb = smem_u32(dsm);

    const int tid    = threadIdx.x;
    const int wid    = tid >> 5;
    const int lane   = tid & 31;
    const int warp_m = wid >> 1;       // 0..3
    const int warp_n = wid & 1;        // 0..1
    const int rowBase = blockIdx.x * 128;

    // loader mapping: 2 threads per row, 32 fp32 cols each
    const int r_local = tid >> 1;
    const int half    = tid & 1;
    const int rg      = rowBase + r_local;
    const float* aSrc =
        X + (size_t)((rg & (B - 1)) * 2 + (rg >> 14)) * D + half * 32;
    const __half* bhSrc = g_cent_h + r_local * D + half * 32;
    const uint32_t aStOff[8] = {
        sw128(r_local * 128 + half * 64 + 0),  sw128(r_local * 128 + half * 64 + 8),
        sw128(r_local * 128 + half * 64 + 16), sw128(r_local * 128 + half * 64 + 24),
        sw128(r_local * 128 + half * 64 + 32), sw128(r_local * 128 + half * 64 + 40),
        sw128(r_local * 128 + half * 64 + 48), sw128(r_local * 128 + half * 64 + 56)};
    const uint32_t bStOff[4] = {
        sw128(r_local * 128 + half * 64 + 0),  sw128(r_local * 128 + half * 64 + 16),
        sw128(r_local * 128 + half * 64 + 32), sw128(r_local * 128 + half * 64 + 48)};

    float c[2][8][4];
    #pragma unroll
    for (int mi = 0; mi < 2; mi++)
        #pragma unroll
        for (int ni = 0; ni < 8; ni++)
            #pragma unroll
            for (int j = 0; j < 4; j++) c[mi][ni][j] = 0.f;
    float nrm = 0.f;

    // ldmatrix lane addressing (within-tile offsets)
    const int a_tile = lane >> 3, a_rr = lane & 7;
    const int l15 = lane & 15;

    // ---- prologue: chunk 0 ----
    float4 abuf[8];
    #pragma unroll
    for (int i = 0; i < 8; i++) abuf[i] = *(const float4*)(aSrc + i * 4);
    {
        uint32_t bh0 = smb + TCBUF;
        #pragma unroll
        for (int i = 0; i < 4; i++)
            CP_ASYNC16(bh0 + bStOff[i], (const char*)(bhSrc + i * 8));
        CP_COMMIT();
    }

    for (int kt = 0; kt < D / KC; kt++) {
        const uint32_t st = smb + (kt & 1) * TCSTAGE;
        const uint32_t Ah = st, Bh = st + TCBUF;

        // convert + STS A(kt) (+ row-norm accumulation)
        #pragma unroll
        for (int i = 0; i < 8; i++) {
            float4 v = abuf[i];
            nrm = fmaf(v.x, v.x, nrm); nrm = fmaf(v.y, v.y, nrm);
            nrm = fmaf(v.z, v.z, nrm); nrm = fmaf(v.w, v.w, nrm);
            __half hx = __float2half(v.x);
            __half hy = __float2half(v.y);
            __half hz = __float2half(v.z);
            __half hw = __float2half(v.w);
            __half2 h01(hx, hy), h23(hz, hw);
            uint2 hv = make_uint2(*(uint32_t*)&h01, *(uint32_t*)&h23);
            asm volatile("st.shared.v2.b32 [%0], {%1,%2};" ::
                         "r"(Ah + aStOff[i]), "r"(hv.x), "r"(hv.y) : "memory");
        }
        CP_WAIT0();          // B(kt) landed
        __syncthreads();     // stage (kt&1) fully populated

        // prefetch chunk kt+1
        if (kt + 1 < D / KC) {
            #pragma unroll
            for (int i = 0; i < 8; i++)
                abuf[i] = *(const float4*)(aSrc + (kt + 1) * KC + i * 4);
            const uint32_t nst = smb + ((kt + 1) & 1) * TCSTAGE;
            #pragma unroll
            for (int i = 0; i < 4; i++)
                CP_ASYNC16(nst + TCBUF + bStOff[i],
                           (const char*)(bhSrc + (kt + 1) * KC + i * 8));
            CP_COMMIT();
        }

        // compute: 4 k16 steps
        #pragma unroll
        for (int ks = 0; ks < 4; ks++) {
            const int kb = ks * 16;
            uint32_t ah[2][4];
            #pragma unroll
            for (int mi = 0; mi < 2; mi++) {
                int mrow = warp_m * 32 + mi * 16 + ((a_tile & 1) << 3) + a_rr;
                int kcol = kb + ((a_tile >> 1) << 3);
                uint32_t off = sw128((uint32_t)(mrow * 128 + kcol * 2));
                LDSM4(ah[mi], Ah + off);
            }
            #pragma unroll
            for (int ni = 0; ni < 8; ni++) {
                int nrow = warp_n * 64 + ni * 8 + (l15 & 7);
                int kcol = kb + ((l15 >> 3) << 3);
                uint32_t boff = sw128((uint32_t)(nrow * 128 + kcol * 2));
                uint32_t bh[2];
                LDSM2(bh, Bh + boff);
                MMA_F16(c[0][ni], ah[0], bh);
                MMA_F16(c[1][ni], ah[1], bh);
            }
        }
        __syncthreads();     // protect stage reuse (STS of kt+2)
    }

    // row norms (pairs of threads share a row)
    nrm += __shfl_xor_sync(0xffffffffu, nrm, 1);
    if (half == 0) g_rownorm[rg] = nrm;

    // epilogue: write C fragments
    const int mq = lane >> 2, nq = (lane & 3) * 2;
    #pragma unroll
    for (int mi = 0; mi < 2; mi++) {
        #pragma unroll
        for (int ni = 0; ni < 8; ni++) {
            int m = rowBase + warp_m * 32 + mi * 16 + mq;
            int n = warp_n * 64 + ni * 8 + nq;
            float2 v0 = make_float2(c[mi][ni][0], c[mi][ni][1]);
            float2 v1 = make_float2(c[mi][ni][2], c[mi][ni][3]);
            *(float2*)(g_sim + (size_t)m * NGRP + n)       = v0;
            *(float2*)(g_sim + (size_t)(m + 8) * NGRP + n) = v1;
        }
    }
}

// ---------------- 5: per-row distance -> sqrt -> group mean accum -----------
__global__ void k_dist() {
    int r = blockIdx.x * blockDim.x + threadIdx.x;
    if (r < NROWS) {
        int b = r & (B - 1);
        int g = g_gid[b];
        float s    = g_sim[(size_t)r * NGRP + g];
        float d2   = g_rownorm[r] - 2.f * s + g_cnorm[g];
        float dist = sqrtf(fmaxf(d2, 0.f));
        atomicAdd(&g_msqrt[g], sqrtf(dist));
    }
}

// ---------------- 6: density (1 block, 128 threads) -------------------------
__global__ void k_density() {
    __shared__ float sd[NGRP];
    __shared__ float sr[NGRP];
    int t = threadIdx.x;
    float cnt  = 2.f * (float)g_cntB[t];
    float dens = (g_msqrt[t] / cnt) / logf(cnt + 10.f);

    sr[t] = dens; __syncthreads();
    for (int s = 64; s > 0; s >>= 1) {
        if (t < s) sr[t] = fmaxf(sr[t], sr[t + s]);
        __syncthreads();
    }
    float dmax = sr[0]; __syncthreads();
    if (cnt <= 1.f) dens = dmax;

    sd[t] = dens; __syncthreads();
    for (int ksz = 2; ksz <= NGRP; ksz <<= 1) {
        for (int j = ksz >> 1; j > 0; j >>= 1) {
            int ixj = t ^ j;
            if (ixj > t) {
                float x = sd[t], y = sd[ixj];
                bool up = ((t & ksz) == 0);
                if ((x > y) == up) { sd[t] = y; sd[ixj] = x; }
            }
            __syncthreads();
        }
    }
    float lo = sd[12]  + 0.7f * (sd[13]  - sd[12]);
    float hi = sd[114] + 0.3f * (sd[115] - sd[114]);
    float dc = fminf(fmaxf(dens, lo), hi);

    sr[t] = dc; __syncthreads();
    for (int s = 64; s > 0; s >>= 1) {
        if (t < s) sr[t] += sr[t + s];
        __syncthreads();
    }
    float mean = sr[0] * (1.f / (float)NGRP);
    g_rdens[t] = mean / (0.1f * dc);
}

// ---------------- 7: loss (one warp per row) + fused finalize ----------------
__global__ void __launch_bounds__(256) k_loss(const int* __restrict__ subj,
                                              const int* __restrict__ lab,
                                              float* __restrict__ out) {
    __shared__ float sdens[NGRP];
    __shared__ float swsum[8];
    int t = threadIdx.x, lane = t & 31, w = t >> 5;
    if (t < NGRP) sdens[t] = g_rdens[t];
    __syncthreads();

    int r = blockIdx.x * 8 + w;
    int b = r & (B - 1);
    int sub = subj[b], la = lab[b];
    const float* row = g_sim + (size_t)r * NGRP;

    float v[4];
    float mx = -1e30f;
    #pragma unroll
    for (int q = 0; q < 4; q++) {
        int g = q * 32 + lane;
        v[q] = row[g] * sdens[g];
        mx = fmaxf(mx, v[q]);
    }
    #pragma unroll
    for (int o = 16; o; o >>= 1) mx = fmaxf(mx, __shfl_xor_sync(0xffffffffu, mx, o));

    float p[4];
    float possum = 0.f, m2 = -1e30f;
    #pragma unroll
    for (int q = 0; q < 4; q++) {
        int g = q * 32 + lane;
        bool msk = ((g >> 3) != sub) && ((g & 7) == la);
        float val = v[q] - mx;
        p[q] = msk ? val : 0.f;
        possum += msk ? val : 0.f;
        m2 = fmaxf(m2, p[q]);
    }
    #pragma unroll
    for (int o = 16; o; o >>= 1) m2 = fmaxf(m2, __shfl_xor_sync(0xffffffffu, m2, o));

    float se = 0.f;
    #pragma unroll
    for (int q = 0; q < 4; q++) se += expf(p[q] - m2);
    #pragma unroll
    for (int o = 16; o; o >>= 1) {
        se     += __shfl_xor_sync(0xffffffffu, se, o);
        possum += __shfl_xor_sync(0xffffffffu, possum, o);
    }
    float lse  = m2 + logf(se);
    float loss = lse - possum * (1.f / 15.f);   // mask.sum = NSUB-1 = 15 always

    if (lane == 0) swsum[w] = loss;
    __syncthreads();
    if (t == 0) {
        float s = 0.f;
        #pragma unroll
        for (int i = 0; i < 8; i++) s += swsum[i];
        atomicAdd(&g_loss, s);
        __threadfence();
        int tk = atomicAdd(&g_ticket, 1);
        if (tk == gridDim.x - 1) {
            out[0] = g_loss * (1.f / (float)NROWS);
        }
    }
}

// ---------------- launcher ----------------------------------------------------
extern "C" void kernel_launch(void* const* d_in, const int* in_sizes, int n_in,
                              void* d_out, int out_size) {
    const float* X    = (const float*)d_in[0];
    const int*   subj = (const int*)  d_in[1];
    const int*   lab  = (const int*)  d_in[2];
    float*       out  = (float*)d_out;

    cudaFuncSetAttribute(k_gemm_mma, cudaFuncAttributeMaxDynamicSharedMemorySize,
                         TC_SMEM);

    k_hist2   <<<NBLK, 256>>>(subj, lab);            // 1 (+init)
    k_scatter <<<NBLK, 256>>>();                     // 2 (+scan)
    k_centroid<<<dim3(4, NGRP, 8), 256>>>(X);        // 3 (+finalize)
    k_gemm_mma<<<NROWS / 128, 256, TC_SMEM>>>(X);    // 4  <- profiled slot
    k_dist    <<<NROWS / 256, 256>>>();              // 5
    k_density <<<1, NGRP>>>();                       // 6
    k_loss    <<<NROWS / 8, 256>>>(subj, lab, out);  // 7
}

// round 13
// speedup vs baseline: 1.0598x; 1.0132x over previous
#include <cuda_runtime.h>
#include <cuda_fp16.h>
#include <math.h>
#include <stdint.h>

// Problem constants
#define B     16384
#define NROWS 32768          // B * C, C = 2
#define D     1024
#define NGRP  128            // N_SUBJECTS * N_LABELS
#define NL    8
#define NSUB  16
#define NBLK  64             // sort blocks (B / 256)

// ---------------- scratch (device globals; no allocation allowed) ----------
__device__ int   g_gid[B];
__device__ int   g_bhist[NBLK * NGRP];
__device__ int   g_cntB[NGRP];
__device__ int   g_off[NGRP + 1];
__device__ int   g_perm[B];
__device__ float g_cent8[8 * NGRP * D];           // per-slice centroid partials (4 MB)
__device__ __align__(16) __half g_cent_h[NGRP * D];   // fp16 centroid (B operand)
__device__ float g_cnorm[NGRP];
__device__ float g_sim[(size_t)NROWS * NGRP];     // 16 MB
__device__ float g_rownorm[NROWS];
__device__ float g_msqrt[NGRP];
__device__ float g_rdens[NGRP];                   // reciprocal density
__device__ float g_loss;
__device__ int   g_ticket;
__device__ int   g_tick_cd[4 * NGRP];             // centroid finalize tickets

// ---------------- helpers (base PTX only — compute_103-safe) ---------------
__device__ __forceinline__ uint32_t smem_u32(const void* p) {
    uint32_t a;
    asm("{ .reg .u64 t; cvta.to.shared.u64 t, %1; cvt.u32.u64 %0, t; }"
        : "=r"(a) : "l"(p));
    return a;
}
__device__ __forceinline__ uint32_t sw128(uint32_t off) {
    return off ^ ((off >> 3) & 0x70);
}
#define CP_ASYNC16(dst, src) \
    asm volatile("cp.async.cg.shared.global [%0], [%1], 16;" \
                 :: "r"(dst), "l"(src) : "memory")
#define CP_COMMIT() asm volatile("cp.async.commit_group;" ::: "memory")
#define CP_WAIT1()  asm volatile("cp.async.wait_group 1;" ::: "memory")

#define LDSM4(r, a)                                                          \
    asm volatile("ldmatrix.sync.aligned.m8n8.x4.shared.b16 {%0,%1,%2,%3}, [%4];" \
        : "=r"((r)[0]), "=r"((r)[1]), "=r"((r)[2]), "=r"((r)[3]) : "r"(a))
#define LDSM2(r, a)                                                          \
    asm volatile("ldmatrix.sync.aligned.m8n8.x2.shared.b16 {%0,%1}, [%2];"   \
        : "=r"((r)[0]), "=r"((r)[1]) : "r"(a))
#define MMA_F16(c, a, bq)                                                    \
    asm volatile("mma.sync.aligned.m16n8k16.row.col.f32.f16.f16.f32 "       \
        "{%0,%1,%2,%3},{%4,%5,%6,%7},{%8,%9},{%0,%1,%2,%3};"                 \
        : "+f"((c)[0]), "+f"((c)[1]), "+f"((c)[2]), "+f"((c)[3])             \
        : "r"((a)[0]), "r"((a)[1]), "r"((a)[2]), "r"((a)[3]),                \
          "r"((bq)[0]), "r"((bq)[1]))

// ---------------- 1: gid + per-block histogram (+ init in block 0) -----------
__global__ void k_hist2(const int* __restrict__ subj, const int* __restrict__ lab) {
    __shared__ int h[NGRP];
    int t = threadIdx.x;
    if (t < NGRP) h[t] = 0;
    if (blockIdx.x == 0) {
        if (t < NGRP) { g_msqrt[t] = 0.f; g_cnorm[t] = 0.f; }
        g_tick_cd[t] = 0;
        g_tick_cd[t + 256] = 0;
        if (t == 0) { g_loss = 0.f; g_ticket = 0; }
    }
    __syncthreads();
    int b = blockIdx.x * 256 + t;
    int g = subj[b] * NL + lab[b];
    g_gid[b] = g;
    atomicAdd(&h[g], 1);
    __syncthreads();
    if (t < NGRP) g_bhist[blockIdx.x * NGRP + t] = h[t];
}

// ---------------- 2: scatter (per-block local scan of g_bhist) ---------------
__global__ void k_scatter() {
    __shared__ int swc[8 * NGRP];
    __shared__ int s_off[NGRP];
    __shared__ int s_base[NGRP];
    int t = threadIdx.x, wid = t >> 5, lane = t & 31;
    for (int i = t; i < 8 * NGRP; i += 256) swc[i] = 0;
    if (t < NGRP) {
        int before = 0, total = 0;
        for (int bk = 0; bk < NBLK; bk++) {
            int hh = g_bhist[bk * NGRP + t];
            before += (bk < (int)blockIdx.x) ? hh : 0;
            total += hh;
        }
        s_off[t] = total;
        s_base[t] = before;
        if (blockIdx.x == 0) g_cntB[t] = total;
    }
    __syncthreads();
    if (t == 0) {
        int a = 0;
        for (int i = 0; i < NGRP; i++) { int c = s_off[i]; s_off[i] = a; a += c; }
    }
    __syncthreads();
    if (t < NGRP) {
        s_base[t] += s_off[t];
        if (blockIdx.x == 0) {
            g_off[t] = s_off[t];
            if (t == 0) g_off[NGRP] = B;
        }
    }
    __syncthreads();
    int b = blockIdx.x * 256 + t;
    int g = g_gid[b];
    unsigned mask = __match_any_sync(0xffffffffu, g);
    unsigned lt = (1u << lane) - 1u;
    int rank = __popc(mask & lt);
    if (rank == 0) swc[wid * NGRP + g] = __popc(mask);
    __syncthreads();
    int pre = 0;
    for (int w = 0; w < wid; w++) pre += swc[w * NGRP + g];
    g_perm[s_base[g] + pre + rank] = b;
}

// ---------------- 3: centroid gather + ticketed finalize ---------------------
__global__ void k_centroid(const float* __restrict__ X) {
    __shared__ float sr[256];
    __shared__ int s_last;
    int g = blockIdx.y;
    int dblk = blockIdx.x;
    int slice = blockIdx.z;
    int t = threadIdx.x;
    int d = dblk * 256 + t;
    int s = g_off[g], e = g_off[g + 1];
    float acc = 0.f;
    int i = s + slice;
    for (; i + 16 <= e; i += 16) {
        const float* p0 = X + (size_t)g_perm[i]     * (2 * D);
        const float* p1 = X + (size_t)g_perm[i + 8] * (2 * D);
        acc += (p0[d] + p0[D + d]) + (p1[d] + p1[D + d]);
    }
    for (; i < e; i += 8) {
        const float* p = X + (size_t)g_perm[i] * (2 * D);
        acc += p[d] + p[D + d];
    }
    g_cent8[(slice * NGRP + g) * D + d] = acc;
    __threadfence();
    __syncthreads();
    if (t == 0) s_last = (atomicAdd(&g_tick_cd[dblk * NGRP + g], 1) == 7) ? 1 : 0;
    __syncthreads();
    if (!s_last) return;
    __threadfence();
    float inv = 1.f / (2.f * (float)g_cntB[g]);
    float c = 0.f;
    #pragma unroll
    for (int sl = 0; sl < 8; sl++) c += g_cent8[(sl * NGRP + g) * D + d];
    c *= inv;
    g_cent_h[g * D + d] = __float2half(c);
    sr[t] = c * c; __syncthreads();
    for (int st = 128; st > 0; st >>= 1) {
        if (t < st) sr[t] += sr[t + st];
        __syncthreads();
    }
    if (t == 0) atomicAdd(&g_cnorm[g], sr[0]);
}

// ---------------- 4: HMMA GEMM  sim = feat @ centroid^T  (+ row norms) -------
// R9 structure, modified: B triple-buffered, ONE barrier per chunk (trailing
// sync removed — skew bounded to 1 iter by the single barrier; A-stage rewrite
// at kt+2 and B-stage rewrite at kt+3 both sit behind it).
#define KC       64
#define TCBUF    16384                 // 128 rows x 128 bytes
#define TC_SMEM  (5 * TCBUF)           // A x2 + B x3 = 80 KB

__global__ void __launch_bounds__(256, 1) k_gemm_mma(const float* __restrict__ X) {
    extern __shared__ __align__(1024) char dsm[];
    const uint32_t smb = smem_u32(dsm);

    const int tid    = threadIdx.x;
    const int wid    = tid >> 5;
    const int lane   = tid & 31;
    const int warp_m = wid >> 1;       // 0..3
    const int warp_n = wid & 1;        // 0..1
    const int rowBase = blockIdx.x * 128;

    // loader mapping: 2 threads per row, 32 fp32 cols each
    const int r_local = tid >> 1;
    const int half    = tid & 1;
    const int rg      = rowBase + r_local;
    const float* aSrc =
        X + (size_t)((rg & (B - 1)) * 2 + (rg >> 14)) * D + half * 32;
    const __half* bhSrc = g_cent_h + r_local * D + half * 32;
    const uint32_t aStOff[8] = {
        sw128(r_local * 128 + half * 64 + 0),  sw128(r_local * 128 + half * 64 + 8),
        sw128(r_local * 128 + half * 64 + 16), sw128(r_local * 128 + half * 64 + 24),
        sw128(r_local * 128 + half * 64 + 32), sw128(r_local * 128 + half * 64 + 40),
        sw128(r_local * 128 + half * 64 + 48), sw128(r_local * 128 + half * 64 + 56)};
    const uint32_t bStOff[4] = {
        sw128(r_local * 128 + half * 64 + 0),  sw128(r_local * 128 + half * 64 + 16),
        sw128(r_local * 128 + half * 64 + 32), sw128(r_local * 128 + half * 64 + 48)};

    float c[2][8][4];
    #pragma unroll
    for (int mi = 0; mi < 2; mi++)
        #pragma unroll
        for (int ni = 0; ni < 8; ni++)
            #pragma unroll
            for (int j = 0; j < 4; j++) c[mi][ni][j] = 0.f;
    float nrm = 0.f;

    // ldmatrix lane addressing (within-tile offsets)
    const int a_tile = lane >> 3, a_rr = lane & 7;
    const int l15 = lane & 15;

    // ---- prologue: A chunk 0 to regs; B chunks 0 and 1 in flight ----
    float4 abuf[8];
    #pragma unroll
    for (int i = 0; i < 8; i++) abuf[i] = *(const float4*)(aSrc + i * 4);
    {
        uint32_t b0 = smb + 2 * TCBUF;        // B stage 0
        #pragma unroll
        for (int i = 0; i < 4; i++)
            CP_ASYNC16(b0 + bStOff[i], (const char*)(bhSrc + i * 8));
        CP_COMMIT();
        uint32_t b1 = smb + 3 * TCBUF;        // B stage 1
        #pragma unroll
        for (int i = 0; i < 4; i++)
            CP_ASYNC16(b1 + bStOff[i], (const char*)(bhSrc + KC + i * 8));
        CP_COMMIT();
    }

    for (int kt = 0; kt < D / KC; kt++) {
        const uint32_t Ah = smb + (kt & 1) * TCBUF;
        const uint32_t Bh = smb + (2 + (kt % 3)) * TCBUF;

        // convert + STS A(kt) (+ row-norm accumulation)
        #pragma unroll
        for (int i = 0; i < 8; i++) {
            float4 v = abuf[i];
            nrm = fmaf(v.x, v.x, nrm); nrm = fmaf(v.y, v.y, nrm);
            nrm = fmaf(v.z, v.z, nrm); nrm = fmaf(v.w, v.w, nrm);
            __half hx = __float2half(v.x);
            __half hy = __float2half(v.y);
            __half hz = __float2half(v.z);
            __half hw = __float2half(v.w);
            __half2 h01(hx, hy), h23(hz, hw);
            uint2 hv = make_uint2(*(uint32_t*)&h01, *(uint32_t*)&h23);
            asm volatile("st.shared.v2.b32 [%0], {%1,%2};" ::
                         "r"(Ah + aStOff[i]), "r"(hv.x), "r"(hv.y) : "memory");
        }
        CP_WAIT1();          // B(kt) landed (B(kt+1) may still fly)
        __syncthreads();     // A(kt) + B(kt) visible to all warps

        // prefetch: A(kt+1) to regs, B(kt+2) via cp.async
        if (kt + 1 < D / KC) {
            #pragma unroll
            for (int i = 0; i < 8; i++)
                abuf[i] = *(const float4*)(aSrc + (kt + 1) * KC + i * 4);
            if (kt + 2 < D / KC) {
                const uint32_t nB = smb + (2 + ((kt + 2) % 3)) * TCBUF;
                #pragma unroll
                for (int i = 0; i < 4; i++)
                    CP_ASYNC16(nB + bStOff[i],
                               (const char*)(bhSrc + (kt + 2) * KC + i * 8));
            }
        }
        CP_COMMIT();         // uniform group count (possibly empty)

        // compute: 4 k16 steps
        #pragma unroll
        for (int ks = 0; ks < 4; ks++) {
            const int kb = ks * 16;
            uint32_t ah[2][4];
            #pragma unroll
            for (int mi = 0; mi < 2; mi++) {
                int mrow = warp_m * 32 + mi * 16 + ((a_tile & 1) << 3) + a_rr;
                int kcol = kb + ((a_tile >> 1) << 3);
                uint32_t off = sw128((uint32_t)(mrow * 128 + kcol * 2));
                LDSM4(ah[mi], Ah + off);
            }
            #pragma unroll
            for (int ni = 0; ni < 8; ni++) {
                int nrow = warp_n * 64 + ni * 8 + (l15 & 7);
                int kcol = kb + ((l15 >> 3) << 3);
                uint32_t boff = sw128((uint32_t)(nrow * 128 + kcol * 2));
                uint32_t bh[2];
                LDSM2(bh, Bh + boff);
                MMA_F16(c[0][ni], ah[0], bh);
                MMA_F16(c[1][ni], ah[1], bh);
            }
        }
        // no trailing sync: next write of A stage (kt+2) / B stage (kt+3)
        // is behind the one barrier per chunk above.
    }

    // row norms (pairs of threads share a row)
    nrm += __shfl_xor_sync(0xffffffffu, nrm, 1);
    if (half == 0) g_rownorm[rg] = nrm;

    // epilogue: write C fragments
    const int mq = lane >> 2, nq = (lane & 3) * 2;
    #pragma unroll
    for (int mi = 0; mi < 2; mi++) {
        #pragma unroll
        for (int ni = 0; ni < 8; ni++) {
            int m = rowBase + warp_m * 32 + mi * 16 + mq;
            int n = warp_n * 64 + ni * 8 + nq;
            float2 v0 = make_float2(c[mi][ni][0], c[mi][ni][1]);
            float2 v1 = make_float2(c[mi][ni][2], c[mi][ni][3]);
            *(float2*)(g_sim + (size_t)m * NGRP + n)       = v0;
            *(float2*)(g_sim + (size_t)(m + 8) * NGRP + n) = v1;
        }
    }
}

// ---------------- 5: per-row distance -> sqrt -> group mean accum -----------
__global__ void k_dist() {
    int r = blockIdx.x * blockDim.x + threadIdx.x;
    if (r < NROWS) {
        int b = r & (B - 1);
        int g = g_gid[b];
        float s    = g_sim[(size_t)r * NGRP + g];
        float d2   = g_rownorm[r] - 2.f * s + g_cnorm[g];
        float dist = sqrtf(fmaxf(d2, 0.f));
        atomicAdd(&g_msqrt[g], sqrtf(dist));
    }
}

// ---------------- 6: density (1 block, 128 threads) -------------------------
__global__ void k_density() {
    __shared__ float sd[NGRP];
    __shared__ float sr[NGRP];
    int t = threadIdx.x;
    float cnt  = 2.f * (float)g_cntB[t];
    float dens = (g_msqrt[t] / cnt) / logf(cnt + 10.f);

    sr[t] = dens; __syncthreads();
    for (int s = 64; s > 0; s >>= 1) {
        if (t < s) sr[t] = fmaxf(sr[t], sr[t + s]);
        __syncthreads();
    }
    float dmax = sr[0]; __syncthreads();
    if (cnt <= 1.f) dens = dmax;

    sd[t] = dens; __syncthreads();
    for (int ksz = 2; ksz <= NGRP; ksz <<= 1) {
        for (int j = ksz >> 1; j > 0; j >>= 1) {
            int ixj = t ^ j;
            if (ixj > t) {
                float x = sd[t], y = sd[ixj];
                bool up = ((t & ksz) == 0);
                if ((x > y) == up) { sd[t] = y; sd[ixj] = x; }
            }
            __syncthreads();
        }
    }
    float lo = sd[12]  + 0.7f * (sd[13]  - sd[12]);
    float hi = sd[114] + 0.3f * (sd[115] - sd[114]);
    float dc = fminf(fmaxf(dens, lo), hi);

    sr[t] = dc; __syncthreads();
    for (int s = 64; s > 0; s >>= 1) {
        if (t < s) sr[t] += sr[t + s];
        __syncthreads();
    }
    float mean = sr[0] * (1.f / (float)NGRP);
    g_rdens[t] = mean / (0.1f * dc);
}

// ---------------- 7: loss (one warp per row) + fused finalize ----------------
__global__ void __launch_bounds__(256) k_loss(const int* __restrict__ subj,
                                              const int* __restrict__ lab,
                                              float* __restrict__ out) {
    __shared__ float sdens[NGRP];
    __shared__ float swsum[8];
    int t = threadIdx.x, lane = t & 31, w = t >> 5;
    if (t < NGRP) sdens[t] = g_rdens[t];
    __syncthreads();

    int r = blockIdx.x * 8 + w;
    int b = r & (B - 1);
    int sub = subj[b], la = lab[b];
    const float* row = g_sim + (size_t)r * NGRP;

    float v[4];
    float mx = -1e30f;
    #pragma unroll
    for (int q = 0; q < 4; q++) {
        int g = q * 32 + lane;
        v[q] = row[g] * sdens[g];
        mx = fmaxf(mx, v[q]);
    }
    #pragma unroll
    for (int o = 16; o; o >>= 1) mx = fmaxf(mx, __shfl_xor_sync(0xffffffffu, mx, o));

    float p[4];
    float possum = 0.f, m2 = -1e30f;
    #pragma unroll
    for (int q = 0; q < 4; q++) {
        int g = q * 32 + lane;
        bool msk = ((g >> 3) != sub) && ((g & 7) == la);
        float val = v[q] - mx;
        p[q] = msk ? val : 0.f;
        possum += msk ? val : 0.f;
        m2 = fmaxf(m2, p[q]);
    }
    #pragma unroll
    for (int o = 16; o; o >>= 1) m2 = fmaxf(m2, __shfl_xor_sync(0xffffffffu, m2, o));

    float se = 0.f;
    #pragma unroll
    for (int q = 0; q < 4; q++) se += expf(p[q] - m2);
    #pragma unroll
    for (int o = 16; o; o >>= 1) {
        se     += __shfl_xor_sync(0xffffffffu, se, o);
        possum += __shfl_xor_sync(0xffffffffu, possum, o);
    }
    float lse  = m2 + logf(se);
    float loss = lse - possum * (1.f / 15.f);   // mask.sum = NSUB-1 = 15 always

    if (lane == 0) swsum[w] = loss;
    __syncthreads();
    if (t == 0) {
        float s = 0.f;
        #pragma unroll
        for (int i = 0; i < 8; i++) s += swsum[i];
        atomicAdd(&g_loss, s);
        __threadfence();
        int tk = atomicAdd(&g_ticket, 1);
        if (tk == gridDim.x - 1) {
            out[0] = g_loss * (1.f / (float)NROWS);
        }
    }
}

// ---------------- launcher ----------------------------------------------------
extern "C" void kernel_launch(void* const* d_in, const int* in_sizes, int n_in,
                              void* d_out, int out_size) {
    const float* X    = (const float*)d_in[0];
    const int*   subj = (const int*)  d_in[1];
    const int*   lab  = (const int*)  d_in[2];
    float*       out  = (float*)d_out;

    cudaFuncSetAttribute(k_gemm_mma, cudaFuncAttributeMaxDynamicSharedMemorySize,
                         TC_SMEM);

    k_hist2   <<<NBLK, 256>>>(subj, lab);            // 1 (+init)
    k_scatter <<<NBLK, 256>>>();                     // 2 (+scan)
    k_centroid<<<dim3(4, NGRP, 8), 256>>>(X);        // 3 (+finalize)
    k_gemm_mma<<<NROWS / 128, 256, TC_SMEM>>>(X);    // 4  <- profiled slot
    k_dist    <<<NROWS / 256, 256>>>();              // 5
    k_density <<<1, NGRP>>>();                       // 6
    k_loss    <<<NROWS / 8, 256>>>(subj, lab, out);  // 7
}

// round 14
// speedup vs baseline: 1.2302x; 1.1607x over previous
#include <cuda_runtime.h>
#include <cuda_fp16.h>
#include <math.h>
#include <stdint.h>

// Problem constants
#define B     16384
#define NROWS 32768          // B * C, C = 2
#define D     1024
#define NGRP  128            // N_SUBJECTS * N_LABELS
#define NL    8
#define NSUB  16
#define NBLK  64             // sort blocks (B / 256)

// ---------------- scratch (device globals; no allocation allowed) ----------
__device__ int   g_gid[B];
__device__ int   g_bhist[NBLK * NGRP];
__device__ int   g_cntB[NGRP];
__device__ int   g_off[NGRP + 1];
__device__ int   g_perm[B];
__device__ float g_cent8[8 * NGRP * D];           // per-slice centroid partials (4 MB)
__device__ __align__(16) __half g_cent_h[NGRP * D];   // fp16 centroid (B operand)
__device__ float g_cnorm[NGRP];
__device__ float g_sim[(size_t)NROWS * NGRP];     // 16 MB
__device__ float g_rownorm[NROWS];
__device__ float g_msqrt[NGRP];
__device__ float g_rdens[NGRP];                   // reciprocal density
__device__ float g_loss;
__device__ int   g_ticket;
__device__ int   g_tick_cd[4 * NGRP];             // centroid finalize tickets

// ---------------- helpers (base PTX only — compute_103-safe) ---------------
__device__ __forceinline__ uint32_t smem_u32(const void* p) {
    uint32_t a;
    asm("{ .reg .u64 t; cvta.to.shared.u64 t, %1; cvt.u32.u64 %0, t; }"
        : "=r"(a) : "l"(p));
    return a;
}
__device__ __forceinline__ uint32_t sw128(uint32_t off) {
    return off ^ ((off >> 3) & 0x70);
}
#define CP_ASYNC16(dst, src) \
    asm volatile("cp.async.cg.shared.global [%0], [%1], 16;" \
                 :: "r"(dst), "l"(src) : "memory")
#define CP_COMMIT() asm volatile("cp.async.commit_group;" ::: "memory")
#define CP_WAIT1()  asm volatile("cp.async.wait_group 1;" ::: "memory")

#define LDSM4(r, a)                                                          \
    asm volatile("ldmatrix.sync.aligned.m8n8.x4.shared.b16 {%0,%1,%2,%3}, [%4];" \
        : "=r"((r)[0]), "=r"((r)[1]), "=r"((r)[2]), "=r"((r)[3]) : "r"(a))
#define LDSM2(r, a)                                                          \
    asm volatile("ldmatrix.sync.aligned.m8n8.x2.shared.b16 {%0,%1}, [%2];"   \
        : "=r"((r)[0]), "=r"((r)[1]) : "r"(a))
#define MMA_F16(c, a, bq)                                                    \
    asm volatile("mma.sync.aligned.m16n8k16.row.col.f32.f16.f16.f32 "       \
        "{%0,%1,%2,%3},{%4,%5,%6,%7},{%8,%9},{%0,%1,%2,%3};"                 \
        : "+f"((c)[0]), "+f"((c)[1]), "+f"((c)[2]), "+f"((c)[3])             \
        : "r"((a)[0]), "r"((a)[1]), "r"((a)[2]), "r"((a)[3]),                \
          "r"((bq)[0]), "r"((bq)[1]))

// ---------------- 1: gid + per-block histogram (+ init in block 0) -----------
__global__ void k_hist2(const int* __restrict__ subj, const int* __restrict__ lab) {
    __shared__ int h[NGRP];
    int t = threadIdx.x;
    if (t < NGRP) h[t] = 0;
    if (blockIdx.x == 0) {
        if (t < NGRP) { g_msqrt[t] = 0.f; g_cnorm[t] = 0.f; }
        g_tick_cd[t] = 0;
        g_tick_cd[t + 256] = 0;
        if (t == 0) { g_loss = 0.f; g_ticket = 0; }
    }
    __syncthreads();
    int b = blockIdx.x * 256 + t;
    int g = subj[b] * NL + lab[b];
    g_gid[b] = g;
    atomicAdd(&h[g], 1);
    __syncthreads();
    if (t < NGRP) g_bhist[blockIdx.x * NGRP + t] = h[t];
}

// ---------------- 2: scatter (per-block local scan of g_bhist) ---------------
__global__ void k_scatter() {
    __shared__ int swc[8 * NGRP];
    __shared__ int s_off[NGRP];
    __shared__ int s_base[NGRP];
    int t = threadIdx.x, wid = t >> 5, lane = t & 31;
    for (int i = t; i < 8 * NGRP; i += 256) swc[i] = 0;
    if (t < NGRP) {
        int before = 0, total = 0;
        for (int bk = 0; bk < NBLK; bk++) {
            int hh = g_bhist[bk * NGRP + t];
            before += (bk < (int)blockIdx.x) ? hh : 0;
            total += hh;
        }
        s_off[t] = total;
        s_base[t] = before;
        if (blockIdx.x == 0) g_cntB[t] = total;
    }
    __syncthreads();
    if (t == 0) {
        int a = 0;
        for (int i = 0; i < NGRP; i++) { int c = s_off[i]; s_off[i] = a; a += c; }
    }
    __syncthreads();
    if (t < NGRP) {
        s_base[t] += s_off[t];
        if (blockIdx.x == 0) {
            g_off[t] = s_off[t];
            if (t == 0) g_off[NGRP] = B;
        }
    }
    __syncthreads();
    int b = blockIdx.x * 256 + t;
    int g = g_gid[b];
    unsigned mask = __match_any_sync(0xffffffffu, g);
    unsigned lt = (1u << lane) - 1u;
    int rank = __popc(mask & lt);
    if (rank == 0) swc[wid * NGRP + g] = __popc(mask);
    __syncthreads();
    int pre = 0;
    for (int w = 0; w < wid; w++) pre += swc[w * NGRP + g];
    g_perm[s_base[g] + pre + rank] = b;
}

// ---------------- 3: centroid gather + ticketed finalize ---------------------
__global__ void k_centroid(const float* __restrict__ X) {
    __shared__ float sr[256];
    __shared__ int s_last;
    int g = blockIdx.y;
    int dblk = blockIdx.x;
    int slice = blockIdx.z;
    int t = threadIdx.x;
    int d = dblk * 256 + t;
    int s = g_off[g], e = g_off[g + 1];
    float acc = 0.f;
    int i = s + slice;
    for (; i + 16 <= e; i += 16) {
        const float* p0 = X + (size_t)g_perm[i]     * (2 * D);
        const float* p1 = X + (size_t)g_perm[i + 8] * (2 * D);
        acc += (p0[d] + p0[D + d]) + (p1[d] + p1[D + d]);
    }
    for (; i < e; i += 8) {
        const float* p = X + (size_t)g_perm[i] * (2 * D);
        acc += p[d] + p[D + d];
    }
    g_cent8[(slice * NGRP + g) * D + d] = acc;
    __threadfence();
    __syncthreads();
    if (t == 0) s_last = (atomicAdd(&g_tick_cd[dblk * NGRP + g], 1) == 7) ? 1 : 0;
    __syncthreads();
    if (!s_last) return;
    __threadfence();
    float inv = 1.f / (2.f * (float)g_cntB[g]);
    float c = 0.f;
    #pragma unroll
    for (int sl = 0; sl < 8; sl++) c += g_cent8[(sl * NGRP + g) * D + d];
    c *= inv;
    g_cent_h[g * D + d] = __float2half(c);
    sr[t] = c * c; __syncthreads();
    for (int st = 128; st > 0; st >>= 1) {
        if (t < st) sr[t] += sr[t + st];
        __syncthreads();
    }
    if (t == 0) atomicAdd(&g_cnorm[g], sr[0]);
}

// ---------------- 4: HMMA GEMM  sim = feat @ centroid^T  (+ row norms) -------
// CTA 128x128, 512 threads: 16 warps as 4x4, warp tile 32x32 (latency hiding).
// K chunks of 64 fp32, A double-buffered + B triple-buffered SW128 smem,
// ONE barrier per chunk (skew bounded to 1 iter).
#define KC       64
#define TCBUF    16384                 // 128 rows x 128 bytes
#define TC_SMEM  (5 * TCBUF)           // A x2 + B x3 = 80 KB

__global__ void __launch_bounds__(512, 1) k_gemm_mma(const float* __restrict__ X) {
    extern __shared__ __align__(1024) char dsm[];
    const uint32_t smb = smem_u32(dsm);

    const int tid    = threadIdx.x;
    const int wid    = tid >> 5;
    const int lane   = tid & 31;
    const int warp_m = wid >> 2;       // 0..3
    const int warp_n = wid & 3;        // 0..3
    const int rowBase = blockIdx.x * 128;

    // loader mapping: 4 threads per row, 16 fp32 cols each
    const int r_local = tid >> 2;      // 0..127
    const int quarter = tid & 3;       // 0..3
    const int rg      = rowBase + r_local;
    const float* aSrc =
        X + (size_t)((rg & (B - 1)) * 2 + (rg >> 14)) * D + quarter * 16;
    const __half* bhSrc = g_cent_h + r_local * D + quarter * 16;
    const uint32_t aStOff[4] = {
        sw128(r_local * 128 + quarter * 32 + 0),
        sw128(r_local * 128 + quarter * 32 + 8),
        sw128(r_local * 128 + quarter * 32 + 16),
        sw128(r_local * 128 + quarter * 32 + 24)};
    const uint32_t bStOff[2] = {
        sw128(r_local * 128 + quarter * 32 + 0),
        sw128(r_local * 128 + quarter * 32 + 16)};

    float c[2][4][4];
    #pragma unroll
    for (int mi = 0; mi < 2; mi++)
        #pragma unroll
        for (int ni = 0; ni < 4; ni++)
            #pragma unroll
            for (int j = 0; j < 4; j++) c[mi][ni][j] = 0.f;
    float nrm = 0.f;

    // ldmatrix lane addressing (within-tile offsets)
    const int a_tile = lane >> 3, a_rr = lane & 7;
    const int l15 = lane & 15;

    // ---- prologue: A chunk 0 to regs; B chunks 0 and 1 in flight ----
    float4 abuf[4];
    #pragma unroll
    for (int i = 0; i < 4; i++) abuf[i] = *(const float4*)(aSrc + i * 4);
    {
        uint32_t b0 = smb + 2 * TCBUF;        // B stage 0
        CP_ASYNC16(b0 + bStOff[0], (const char*)bhSrc);
        CP_ASYNC16(b0 + bStOff[1], (const char*)(bhSrc + 8));
        CP_COMMIT();
        uint32_t b1 = smb + 3 * TCBUF;        // B stage 1
        CP_ASYNC16(b1 + bStOff[0], (const char*)(bhSrc + KC));
        CP_ASYNC16(b1 + bStOff[1], (const char*)(bhSrc + KC + 8));
        CP_COMMIT();
    }

    for (int kt = 0; kt < D / KC; kt++) {
        const uint32_t Ah = smb + (kt & 1) * TCBUF;
        const uint32_t Bh = smb + (2 + (kt % 3)) * TCBUF;

        // convert + STS A(kt) (+ row-norm accumulation)
        #pragma unroll
        for (int i = 0; i < 4; i++) {
            float4 v = abuf[i];
            nrm = fmaf(v.x, v.x, nrm); nrm = fmaf(v.y, v.y, nrm);
            nrm = fmaf(v.z, v.z, nrm); nrm = fmaf(v.w, v.w, nrm);
            __half hx = __float2half(v.x);
            __half hy = __float2half(v.y);
            __half hz = __float2half(v.z);
            __half hw = __float2half(v.w);
            __half2 h01(hx, hy), h23(hz, hw);
            uint2 hv = make_uint2(*(uint32_t*)&h01, *(uint32_t*)&h23);
            asm volatile("st.shared.v2.b32 [%0], {%1,%2};" ::
                         "r"(Ah + aStOff[i]), "r"(hv.x), "r"(hv.y) : "memory");
        }
        CP_WAIT1();          // B(kt) landed (B(kt+1) may still fly)
        __syncthreads();     // A(kt) + B(kt) visible to all warps

        // prefetch: A(kt+1) to regs, B(kt+2) via cp.async
        if (kt + 1 < D / KC) {
            #pragma unroll
            for (int i = 0; i < 4; i++)
                abuf[i] = *(const float4*)(aSrc + (kt + 1) * KC + i * 4);
            if (kt + 2 < D / KC) {
                const uint32_t nB = smb + (2 + ((kt + 2) % 3)) * TCBUF;
                CP_ASYNC16(nB + bStOff[0], (const char*)(bhSrc + (kt + 2) * KC));
                CP_ASYNC16(nB + bStOff[1], (const char*)(bhSrc + (kt + 2) * KC + 8));
            }
        }
        CP_COMMIT();         // uniform group count (possibly empty)

        // compute: 4 k16 steps
        #pragma unroll
        for (int ks = 0; ks < 4; ks++) {
            const int kb = ks * 16;
            uint32_t ah[2][4];
            #pragma unroll
            for (int mi = 0; mi < 2; mi++) {
                int mrow = warp_m * 32 + mi * 16 + ((a_tile & 1) << 3) + a_rr;
                int kcol = kb + ((a_tile >> 1) << 3);
                uint32_t off = sw128((uint32_t)(mrow * 128 + kcol * 2));
                LDSM4(ah[mi], Ah + off);
            }
            #pragma unroll
            for (int ni = 0; ni < 4; ni++) {
                int nrow = warp_n * 32 + ni * 8 + (l15 & 7);
                int kcol = kb + ((l15 >> 3) << 3);
                uint32_t boff = sw128((uint32_t)(nrow * 128 + kcol * 2));
                uint32_t bh[2];
                LDSM2(bh, Bh + boff);
                MMA_F16(c[0][ni], ah[0], bh);
                MMA_F16(c[1][ni], ah[1], bh);
            }
        }
        // no trailing sync: next writes of A stage (kt+2) / B stage (kt+3)
        // sit behind the one barrier per chunk above.
    }

    // row norms (4 threads share a row)
    nrm += __shfl_xor_sync(0xffffffffu, nrm, 1);
    nrm += __shfl_xor_sync(0xffffffffu, nrm, 2);
    if (quarter == 0) g_rownorm[rg] = nrm;

    // epilogue: write C fragments
    const int mq = lane >> 2, nq = (lane & 3) * 2;
    #pragma unroll
    for (int mi = 0; mi < 2; mi++) {
        #pragma unroll
        for (int ni = 0; ni < 4; ni++) {
            int m = rowBase + warp_m * 32 + mi * 16 + mq;
            int n = warp_n * 32 + ni * 8 + nq;
            float2 v0 = make_float2(c[mi][ni][0], c[mi][ni][1]);
            float2 v1 = make_float2(c[mi][ni][2], c[mi][ni][3]);
            *(float2*)(g_sim + (size_t)m * NGRP + n)       = v0;
            *(float2*)(g_sim + (size_t)(m + 8) * NGRP + n) = v1;
        }
    }
}

// ---------------- 5: per-row distance -> sqrt -> group mean accum -----------
__global__ void k_dist() {
    int r = blockIdx.x * blockDim.x + threadIdx.x;
    if (r < NROWS) {
        int b = r & (B - 1);
        int g = g_gid[b];
        float s    = g_sim[(size_t)r * NGRP + g];
        float d2   = g_rownorm[r] - 2.f * s + g_cnorm[g];
        float dist = sqrtf(fmaxf(d2, 0.f));
        atomicAdd(&g_msqrt[g], sqrtf(dist));
    }
}

// ---------------- 6: density (1 block, 128 threads) -------------------------
__global__ void k_density() {
    __shared__ float sd[NGRP];
    __shared__ float sr[NGRP];
    int t = threadIdx.x;
    float cnt  = 2.f * (float)g_cntB[t];
    float dens = (g_msqrt[t] / cnt) / logf(cnt + 10.f);

    sr[t] = dens; __syncthreads();
    for (int s = 64; s > 0; s >>= 1) {
        if (t < s) sr[t] = fmaxf(sr[t], sr[t + s]);
        __syncthreads();
    }
    float dmax = sr[0]; __syncthreads();
    if (cnt <= 1.f) dens = dmax;

    sd[t] = dens; __syncthreads();
    for (int ksz = 2; ksz <= NGRP; ksz <<= 1) {
        for (int j = ksz >> 1; j > 0; j >>= 1) {
            int ixj = t ^ j;
            if (ixj > t) {
                float x = sd[t], y = sd[ixj];
                bool up = ((t & ksz) == 0);
                if ((x > y) == up) { sd[t] = y; sd[ixj] = x; }
            }
            __syncthreads();
        }
    }
    float lo = sd[12]  + 0.7f * (sd[13]  - sd[12]);
    float hi = sd[114] + 0.3f * (sd[115] - sd[114]);
    float dc = fminf(fmaxf(dens, lo), hi);

    sr[t] = dc; __syncthreads();
    for (int s = 64; s > 0; s >>= 1) {
        if (t < s) sr[t] += sr[t + s];
        __syncthreads();
    }
    float mean = sr[0] * (1.f / (float)NGRP);
    g_rdens[t] = mean / (0.1f * dc);
}

// ---------------- 7: loss (one warp per row) + fused finalize ----------------
__global__ void __launch_bounds__(256) k_loss(const int* __restrict__ subj,
                                              const int* __restrict__ lab,
                                              float* __restrict__ out) {
    __shared__ float sdens[NGRP];
    __shared__ float swsum[8];
    int t = threadIdx.x, lane = t & 31, w = t >> 5;
    if (t < NGRP) sdens[t] = g_rdens[t];
    __syncthreads();

    int r = blockIdx.x * 8 + w;
    int b = r & (B - 1);
    int sub = subj[b], la = lab[b];
    const float* row = g_sim + (size_t)r * NGRP;

    float v[4];
    float mx = -1e30f;
    #pragma unroll
    for (int q = 0; q < 4; q++) {
        int g = q * 32 + lane;
        v[q] = row[g] * sdens[g];
        mx = fmaxf(mx, v[q]);
    }
    #pragma unroll
    for (int o = 16; o; o >>= 1) mx = fmaxf(mx, __shfl_xor_sync(0xffffffffu, mx, o));

    float p[4];
    float possum = 0.f, m2 = -1e30f;
    #pragma unroll
    for (int q = 0; q < 4; q++) {
        int g = q * 32 + lane;
        bool msk = ((g >> 3) != sub) && ((g & 7) == la);
        float val = v[q] - mx;
        p[q] = msk ? val : 0.f;
        possum += msk ? val : 0.f;
        m2 = fmaxf(m2, p[q]);
    }
    #pragma unroll
    for (int o = 16; o; o >>= 1) m2 = fmaxf(m2, __shfl_xor_sync(0xffffffffu, m2, o));

    float se = 0.f;
    #pragma unroll
    for (int q = 0; q < 4; q++) se += expf(p[q] - m2);
    #pragma unroll
    for (int o = 16; o; o >>= 1) {
        se     += __shfl_xor_sync(0xffffffffu, se, o);
        possum += __shfl_xor_sync(0xffffffffu, possum, o);
    }
    float lse  = m2 + logf(se);
    float loss = lse - possum * (1.f / 15.f);   // mask.sum = NSUB-1 = 15 always

    if (lane == 0) swsum[w] = loss;
    __syncthreads();
    if (t == 0) {
        float s = 0.f;
        #pragma unroll
        for (int i = 0; i < 8; i++) s += swsum[i];
        atomicAdd(&g_loss, s);
        __threadfence();
        int tk = atomicAdd(&g_ticket, 1);
        if (tk == gridDim.x - 1) {
            out[0] = g_loss * (1.f / (float)NROWS);
        }
    }
}

// ---------------- launcher ----------------------------------------------------
extern "C" void kernel_launch(void* const* d_in, const int* in_sizes, int n_in,
                              void* d_out, int out_size) {
    const float* X    = (const float*)d_in[0];
    const int*   subj = (const int*)  d_in[1];
    const int*   lab  = (const int*)  d_in[2];
    float*       out  = (float*)d_out;

    cudaFuncSetAttribute(k_gemm_mma, cudaFuncAttributeMaxDynamicSharedMemorySize,
                         TC_SMEM);

    k_hist2   <<<NBLK, 256>>>(subj, lab);            // 1 (+init)
    k_scatter <<<NBLK, 256>>>();                     // 2 (+scan)
    k_centroid<<<dim3(4, NGRP, 8), 256>>>(X);        // 3 (+finalize)
    k_gemm_mma<<<NROWS / 128, 512, TC_SMEM>>>(X);    // 4  <- profiled slot
    k_dist    <<<NROWS / 256, 256>>>();              // 5
    k_density <<<1, NGRP>>>();                       // 6
    k_loss    <<<NROWS / 8, 256>>>(subj, lab, out);  // 7
}